// round 1
// baseline (speedup 1.0000x reference)
#include <cuda_runtime.h>
#include <cuda_bf16.h>

#define QBINS   20
#define NTHR    19            // thresholds b = 1..19
#define ROWS    64
#define ROWLEN  1000000
#define ROWLEN4 (ROWLEN / 4)  // 250000 float4 per row
#define BPR     18            // blocks per row
#define TPB     256

// Scratch: cumulative counts C[row][b-1] = #{x in row : x >= T_b}, b = 1..19
__device__ int g_cum[ROWS][NTHR];

__global__ void zero_kernel() {
    int i = blockIdx.x * blockDim.x + threadIdx.x;
    if (i < ROWS * NTHR) ((int*)g_cum)[i] = 0;
}

// Minimal float t such that __fmul_rn(t, 20.0f) >= (float)b.
// This makes (x >= t) exactly equivalent to floor(fl(20*x)) >= b,
// matching the reference's fp32 rounding at bin boundaries.
__device__ __forceinline__ float thresh_for(int b) {
    float fb = (float)b;
    float t  = (float)((double)b * 0.05);
    // step down while property holds (t stays positive, bits monotone)
    while (__fmul_rn(t, 20.0f) >= fb) {
        t = __uint_as_float(__float_as_uint(t) - 1u);
    }
    // step up to the minimal t with the property
    while (__fmul_rn(t, 20.0f) < fb) {
        t = __uint_as_float(__float_as_uint(t) + 1u);
    }
    return t;
}

__global__ __launch_bounds__(TPB) void hist_kernel(const float* __restrict__ in) {
    const int row = blockIdx.y;
    const float4* __restrict__ rowp =
        (const float4*)(in + (size_t)row * ROWLEN);

    float T[NTHR];
#pragma unroll
    for (int b = 0; b < NTHR; b++) T[b] = thresh_for(b + 1);

    unsigned cum[NTHR];
#pragma unroll
    for (int b = 0; b < NTHR; b++) cum[b] = 0u;

    const int stride = BPR * TPB;                    // 4608
    const int ITERS  = (ROWLEN4 + stride - 1) / stride;  // 55, warp-uniform
    int i = blockIdx.x * TPB + threadIdx.x;

    for (int k = 0; k < ITERS; k++) {
        // Sentinel -1: fails every threshold -> contributes only to bin 0,
        // which is derived as L - C_1 and thus never sees fake elements.
        float4 v = make_float4(-1.0f, -1.0f, -1.0f, -1.0f);
        if (i < ROWLEN4) v = rowp[i];

#pragma unroll
        for (int b = 0; b < NTHR; b++) {
            unsigned m0 = __ballot_sync(0xffffffffu, v.x >= T[b]);
            unsigned m1 = __ballot_sync(0xffffffffu, v.y >= T[b]);
            unsigned m2 = __ballot_sync(0xffffffffu, v.z >= T[b]);
            unsigned m3 = __ballot_sync(0xffffffffu, v.w >= T[b]);
            cum[b] += (unsigned)((__popc(m0) + __popc(m1)) +
                                 (__popc(m2) + __popc(m3)));
        }
        i += stride;
    }

    // Block-level reduction: all lanes of a warp hold identical cum[]
    __shared__ unsigned s[TPB / 32][NTHR];
    const int wid  = threadIdx.x >> 5;
    const int lane = threadIdx.x & 31;
    if (lane == 0) {
#pragma unroll
        for (int b = 0; b < NTHR; b++) s[wid][b] = cum[b];
    }
    __syncthreads();

    if (threadIdx.x < NTHR) {
        unsigned tot = 0;
#pragma unroll
        for (int w = 0; w < TPB / 32; w++) tot += s[w][threadIdx.x];
        atomicAdd(&g_cum[row][threadIdx.x], (int)tot);
    }
}

__global__ void entropy_kernel(float* __restrict__ out) {
    __shared__ float partial[ROWS];
    const int r = threadIdx.x;
    float ent = 0.0f;
    if (r < ROWS) {
        int cumv[QBINS + 1];
        cumv[0] = ROWLEN;
#pragma unroll
        for (int b = 1; b <= NTHR; b++) cumv[b] = g_cum[r][b - 1];
        cumv[QBINS] = 0;

        const float invL = 1.0f / (float)ROWLEN;
#pragma unroll
        for (int b = 0; b < QBINS; b++) {
            int h = cumv[b] - cumv[b + 1];
            if (h > 0) {
                float p = (float)h * invL;
                ent -= p * log2f(p);
            }
        }
    }
    partial[threadIdx.x] = ent;
    __syncthreads();
    if (threadIdx.x == 0) {
        float sum = 0.0f;
        for (int t = 0; t < ROWS; t++) sum += partial[t];
        out[0] = sum;
    }
}

extern "C" void kernel_launch(void* const* d_in, const int* in_sizes, int n_in,
                              void* d_out, int out_size) {
    (void)in_sizes; (void)n_in; (void)out_size;
    const float* in = (const float*)d_in[0];
    float* out = (float*)d_out;

    zero_kernel<<<(ROWS * NTHR + 255) / 256, 256>>>();
    hist_kernel<<<dim3(BPR, ROWS), TPB>>>(in);
    entropy_kernel<<<1, ROWS>>>(out);
}

// round 3
// speedup vs baseline: 3.1847x; 3.1847x over previous
#include <cuda_runtime.h>
#include <cuda_bf16.h>

#define QBINS    20
#define NSLOT    21            // slot 20 = trash (sentinels + fl(20x)==20 edge)
#define ROWS     64
#define ROWLEN   1000000
#define ROWLEN4  (ROWLEN / 4)  // 250000 float4 per row
#define BPR      8             // blocks per row
#define CHUNK4   (ROWLEN4 / BPR)   // 31250 float4 per block
#define TPB      256
#define ITERS    ((CHUNK4 + TPB - 1) / TPB)  // 123

// Per-block partial histograms (overwritten every call -> no zeroing kernel)
__device__ int g_part[ROWS][BPR][QBINS];

__device__ __forceinline__ int bin_of(float x) {
    // floor(fl_RN(20*x)) computed bit-exactly:
    // m = RN(20x) is representable; m + 2^23 is an exact sum in [2^23, 2^23+20];
    // RZ truncates the fraction -> low bits hold floor(m).
    float y = __fadd_rz(__fmul_rn(x, 20.0f), 8388608.0f);  // 2^23
    return __float_as_int(y) - 0x4B000000;
}

__global__ __launch_bounds__(TPB) void hist_kernel(const float* __restrict__ in) {
    __shared__ int h[NSLOT * TPB];
    __shared__ int wsum[TPB / 32][QBINS];

    const int tid = threadIdx.x;
#pragma unroll
    for (int i = tid; i < NSLOT * TPB; i += TPB) h[i] = 0;
    __syncthreads();

    const int row = blockIdx.y;
    const float4* __restrict__ p =
        (const float4*)(in + (size_t)row * ROWLEN) + (size_t)blockIdx.x * CHUNK4;

    for (int k = 0; k < ITERS; k++) {
        int i = k * TPB + tid;
        // Sentinel 1.0f -> bin 20 (trash slot), never counted.
        float4 v = make_float4(1.0f, 1.0f, 1.0f, 1.0f);
        if (i < CHUNK4) v = p[i];

        h[bin_of(v.x) * TPB + tid] += 1;
        h[bin_of(v.y) * TPB + tid] += 1;
        h[bin_of(v.z) * TPB + tid] += 1;
        h[bin_of(v.w) * TPB + tid] += 1;
    }
    __syncthreads();

    // Block reduction: per bin, sum 256 private counters.
    const int wid  = tid >> 5;
    const int lane = tid & 31;
#pragma unroll
    for (int b = 0; b < QBINS; b++) {
        int v = h[b * TPB + tid];               // conflict-free (bank = lane)
        v = __reduce_add_sync(0xffffffffu, v);  // REDUX.SUM
        if (lane == 0) wsum[wid][b] = v;
    }
    __syncthreads();

    if (tid < QBINS) {
        int tot = 0;
#pragma unroll
        for (int w = 0; w < TPB / 32; w++) tot += wsum[w][tid];
        g_part[row][blockIdx.x][tid] = tot;
    }
}

__global__ void entropy_kernel(float* __restrict__ out) {
    __shared__ float partial[ROWS];
    const int r = threadIdx.x;
    float ent = 0.0f;
    const float invL = 1.0f / (float)ROWLEN;
#pragma unroll
    for (int b = 0; b < QBINS; b++) {
        int c = 0;
#pragma unroll
        for (int blk = 0; blk < BPR; blk++) c += g_part[r][blk][b];
        if (c > 0) {
            float pr = (float)c * invL;
            ent -= pr * log2f(pr);
        }
    }
    partial[r] = ent;
    __syncthreads();
    if (r == 0) {
        float s = 0.0f;
        for (int t = 0; t < ROWS; t++) s += partial[t];
        out[0] = s;
    }
}

extern "C" void kernel_launch(void* const* d_in, const int* in_sizes, int n_in,
                              void* d_out, int out_size) {
    (void)in_sizes; (void)n_in; (void)out_size;
    const float* in = (const float*)d_in[0];
    float* out = (float*)d_out;

    hist_kernel<<<dim3(BPR, ROWS), TPB>>>(in);
    entropy_kernel<<<1, ROWS>>>(out);
}

// round 7
// speedup vs baseline: 3.6921x; 1.1593x over previous
#include <cuda_runtime.h>
#include <cuda_bf16.h>

#define QBINS    20
#define NSLOT    21            // slot 20 = trash (sentinels + fl(20x)==20 edge)
#define ROWS     64
#define ROWLEN   1000000
#define ROWLEN4  (ROWLEN / 4)  // 250000 float4 per row
#define BPR      8             // blocks per row
#define NBLOCKS  (ROWS * BPR)  // 512
#define CHUNK4   (ROWLEN4 / BPR)   // 31250 float4 per block
#define TPB      256
#define ITERS    ((CHUNK4 + TPB - 1) / TPB)  // 123

__device__ int g_part[ROWS][BPR][QBINS];
__device__ unsigned g_done;    // zero-init at load; last block resets to 0 each run

__device__ __forceinline__ int bin_of(float x) {
    // floor(fl_RN(20*x)) bit-exactly: RN(20x)+2^23 is an exact sum; RZ truncates.
    float y = __fadd_rz(__fmul_rn(x, 20.0f), 8388608.0f);  // 2^23
    return __float_as_int(y) - 0x4B000000;
}

__global__ __launch_bounds__(TPB) void fused_kernel(const float* __restrict__ in,
                                                    float* __restrict__ out) {
    // Two sub-histograms: (x,y) -> hA, (z,w) -> hB. Halves the serialized
    // aliasing RMW chain vs one array.
    __shared__ int hA[NSLOT * TPB];
    __shared__ int hB[NSLOT * TPB];
    __shared__ int wsum[TPB / 32][QBINS];
    __shared__ float rowent[ROWS];
    __shared__ unsigned s_last;

    const int tid = threadIdx.x;
#pragma unroll
    for (int i = tid; i < NSLOT * TPB; i += TPB) { hA[i] = 0; hB[i] = 0; }
    __syncthreads();

    const int row = blockIdx.x >> 3;
    const int blk = blockIdx.x & 7;
    const float4* __restrict__ p =
        (const float4*)(in + (size_t)row * ROWLEN) + (size_t)blk * CHUNK4;

    for (int k = 0; k < ITERS; k++) {
        int i = k * TPB + tid;
        float4 v = make_float4(1.0f, 1.0f, 1.0f, 1.0f);  // sentinel -> bin 20
        if (i < CHUNK4) v = __ldcs(&p[i]);

        hA[bin_of(v.x) * TPB + tid] += 1;
        hB[bin_of(v.z) * TPB + tid] += 1;
        hA[bin_of(v.y) * TPB + tid] += 1;
        hB[bin_of(v.w) * TPB + tid] += 1;
    }
    __syncthreads();

    // Block reduction: per bin sum 256 private counters (bank = lane, conflict-free)
    const int wid  = tid >> 5;
    const int lane = tid & 31;
#pragma unroll
    for (int b = 0; b < QBINS; b++) {
        int v = hA[b * TPB + tid] + hB[b * TPB + tid];
        v = __reduce_add_sync(0xffffffffu, v);
        if (lane == 0) wsum[wid][b] = v;
    }
    __syncthreads();

    if (tid < QBINS) {
        int tot = 0;
#pragma unroll
        for (int w = 0; w < TPB / 32; w++) tot += wsum[w][tid];
        g_part[row][blk][tid] = tot;
    }

    // ---- last-block-done: fold entropy epilogue into this launch ----
    __threadfence();
    if (tid == 0) s_last = (atomicAdd(&g_done, 1u) == NBLOCKS - 1u);
    __syncthreads();
    if (!s_last) return;

    if (tid == 0) g_done = 0u;   // reset for next graph replay (determinism)

    float ent = 0.0f;
    if (tid < ROWS) {
        const float invL = 1.0f / (float)ROWLEN;
#pragma unroll
        for (int b = 0; b < QBINS; b++) {
            int c = 0;
#pragma unroll
            for (int k = 0; k < BPR; k++) c += __ldcg(&g_part[tid][k][b]);
            if (c > 0) {
                float pr = (float)c * invL;
                ent -= pr * log2f(pr);
            }
        }
        rowent[tid] = ent;
    }
    __syncthreads();
    if (tid == 0) {
        float s = 0.0f;
#pragma unroll
        for (int r = 0; r < ROWS; r++) s += rowent[r];
        out[0] = s;
    }
}

extern "C" void kernel_launch(void* const* d_in, const int* in_sizes, int n_in,
                              void* d_out, int out_size) {
    (void)in_sizes; (void)n_in; (void)out_size;
    const float* in = (const float*)d_in[0];
    float* out = (float*)d_out;
    fused_kernel<<<NBLOCKS, TPB>>>(in, out);
}

// round 9
// speedup vs baseline: 4.6594x; 1.2620x over previous
#include <cuda_runtime.h>
#include <cuda_bf16.h>

#define QBINS    20
#define NSLOT    21            // slot 20 = trash (sentinels + fl(20x)==20 edge)
#define NPAIR    11            // packed: 2 bins per 32-bit word
#define ROWS     64
#define ROWLEN   1000000
#define ROWLEN4  (ROWLEN / 4)  // 250000 float4 per row
#define BPR      16            // blocks per row
#define NBLOCKS  (ROWS * BPR)  // 1024
#define CHUNK4   (ROWLEN4 / BPR)   // 15625 float4 per block
#define TPB      256
#define PITERS   31            // 31 * 2 * 256 = 15872 >= 15625

__device__ int g_part[ROWS][BPR][QBINS];
__device__ unsigned g_done;    // zero-init at load; last block resets each run

__device__ __forceinline__ int bin_of(float x) {
    // floor(fl_RN(20*x)) bit-exactly: RN(20x)+2^23 is an exact sum; RZ truncates.
    float y = __fadd_rz(__fmul_rn(x, 20.0f), 8388608.0f);  // 2^23
    return __float_as_int(y) - 0x4B000000;
}

__device__ __forceinline__ void bump(int* h, int bin, int tid) {
    h[(bin >> 1) * TPB + tid] += 1 << ((bin & 1) << 4);
}

__global__ __launch_bounds__(TPB) void fused_kernel(const float* __restrict__ in,
                                                    float* __restrict__ out) {
    // Two packed sub-histograms: (x,y)->hA, (z,w)->hB. 16-bit halves, 2 bins/word.
    __shared__ int hA[NPAIR * TPB];
    __shared__ int hB[NPAIR * TPB];
    __shared__ int wsum[TPB / 32][QBINS];
    __shared__ float rowent[ROWS];
    __shared__ unsigned s_last;

    const int tid = threadIdx.x;
#pragma unroll
    for (int i = tid; i < NPAIR * TPB; i += TPB) { hA[i] = 0; hB[i] = 0; }
    __syncthreads();

    const int row = blockIdx.x >> 4;
    const int blk = blockIdx.x & 15;
    const float4* __restrict__ p =
        (const float4*)(in + (size_t)row * ROWLEN) + (size_t)blk * CHUNK4;

    for (int k = 0; k < PITERS; k++) {
        int i0 = (2 * k) * TPB + tid;
        int i1 = i0 + TPB;
        float4 a = make_float4(1.0f, 1.0f, 1.0f, 1.0f);  // sentinel -> bin 20
        float4 b = make_float4(1.0f, 1.0f, 1.0f, 1.0f);
        if (i0 < CHUNK4) a = __ldcs(&p[i0]);
        if (i1 < CHUNK4) b = __ldcs(&p[i1]);

        bump(hA, bin_of(a.x), tid);
        bump(hB, bin_of(a.z), tid);
        bump(hA, bin_of(a.y), tid);
        bump(hB, bin_of(a.w), tid);
        bump(hA, bin_of(b.x), tid);
        bump(hB, bin_of(b.z), tid);
        bump(hA, bin_of(b.y), tid);
        bump(hB, bin_of(b.w), tid);
    }
    __syncthreads();

    // Block reduction: per bin sum 256 private counters (bank = lane, conflict-free)
    const int wid  = tid >> 5;
    const int lane = tid & 31;
#pragma unroll
    for (int b = 0; b < QBINS; b++) {
        int wA = hA[(b >> 1) * TPB + tid];
        int wB = hB[(b >> 1) * TPB + tid];
        int sh = (b & 1) << 4;
        int v = ((wA >> sh) & 0xFFFF) + ((wB >> sh) & 0xFFFF);
        v = __reduce_add_sync(0xffffffffu, v);
        if (lane == 0) wsum[wid][b] = v;
    }
    __syncthreads();

    if (tid < QBINS) {
        int tot = 0;
#pragma unroll
        for (int w = 0; w < TPB / 32; w++) tot += wsum[w][tid];
        g_part[row][blk][tid] = tot;
    }

    // ---- last-block-done: entropy epilogue in the same launch ----
    __threadfence();
    if (tid == 0) s_last = (atomicAdd(&g_done, 1u) == NBLOCKS - 1u);
    __syncthreads();
    if (!s_last) return;

    if (tid == 0) g_done = 0u;   // reset for next graph replay (determinism)

    float ent = 0.0f;
    if (tid < ROWS) {
        const float invL = 1.0f / (float)ROWLEN;
#pragma unroll
        for (int b = 0; b < QBINS; b++) {
            int c = 0;
#pragma unroll
            for (int k = 0; k < BPR; k++) c += __ldcg(&g_part[tid][k][b]);
            if (c > 0) {
                float pr = (float)c * invL;
                ent -= pr * log2f(pr);
            }
        }
        rowent[tid] = ent;
    }
    __syncthreads();
    if (tid == 0) {
        float s = 0.0f;
#pragma unroll
        for (int r = 0; r < ROWS; r++) s += rowent[r];
        out[0] = s;
    }
}

extern "C" void kernel_launch(void* const* d_in, const int* in_sizes, int n_in,
                              void* d_out, int out_size) {
    (void)in_sizes; (void)n_in; (void)out_size;
    const float* in = (const float*)d_in[0];
    float* out = (float*)d_out;
    fused_kernel<<<NBLOCKS, TPB>>>(in, out);
}